// round 10
// baseline (speedup 1.0000x reference)
#include <cuda_runtime.h>
#include <cuda_fp16.h>

#define BB  2
#define SS  2048
#define DD  1024
#define HH  1024
#define NHH 16
#define DHH 64

// ---------------------------------------------------------------------------
// Static scratch
// ---------------------------------------------------------------------------
__device__ __half g_A16[3][BB * SS * DD];          // fp16 KEY, QUERY, VALUE
__device__ __half g_W16[4][HH * DD];               // fp16 Wk, Wq, Wv, Wo
__device__ __half g_Kh[BB * NHH * SS * DHH];       // head-split projections
__device__ __half g_Qh[BB * NHH * SS * DHH];
__device__ __half g_Vh[BB * NHH * SS * DHH];
__device__ __half g_Xt[BB * HH * SS];              // X transposed [b][c][s]

// ---------------------------------------------------------------------------
// PTX helpers
// ---------------------------------------------------------------------------
__device__ __forceinline__ unsigned sptr(const void* p) {
    unsigned a;
    asm("{.reg .u64 t; cvta.to.shared.u64 t, %1; cvt.u32.u64 %0, t;}" : "=r"(a) : "l"(p));
    return a;
}
__device__ __forceinline__ void ldsm4(unsigned& r0, unsigned& r1, unsigned& r2, unsigned& r3, unsigned a) {
    asm volatile("ldmatrix.sync.aligned.m8n8.x4.shared.b16 {%0,%1,%2,%3},[%4];\n"
                 : "=r"(r0), "=r"(r1), "=r"(r2), "=r"(r3) : "r"(a));
}
__device__ __forceinline__ void ldsm4t(unsigned& r0, unsigned& r1, unsigned& r2, unsigned& r3, unsigned a) {
    asm volatile("ldmatrix.sync.aligned.m8n8.x4.trans.shared.b16 {%0,%1,%2,%3},[%4];\n"
                 : "=r"(r0), "=r"(r1), "=r"(r2), "=r"(r3) : "r"(a));
}
__device__ __forceinline__ void mma16816(float* c, unsigned a0, unsigned a1, unsigned a2, unsigned a3,
                                         unsigned b0, unsigned b1) {
    asm volatile("mma.sync.aligned.m16n8k16.row.col.f32.f16.f16.f32 "
                 "{%0,%1,%2,%3},{%4,%5,%6,%7},{%8,%9},{%0,%1,%2,%3};\n"
                 : "+f"(c[0]), "+f"(c[1]), "+f"(c[2]), "+f"(c[3])
                 : "r"(a0), "r"(a1), "r"(a2), "r"(a3), "r"(b0), "r"(b1));
}
__device__ __forceinline__ void cpa16(unsigned d, const void* s) {
    asm volatile("cp.async.cg.shared.global [%0],[%1],16;\n" :: "r"(d), "l"(s));
}
__device__ __forceinline__ void cpa_commit() { asm volatile("cp.async.commit_group;\n"); }
template <int N> __device__ __forceinline__ void cpa_wait() {
    asm volatile("cp.async.wait_group %0;\n" :: "n"(N));
}

// ---------------------------------------------------------------------------
// Fused fp32->fp16 conversion, 2 float4 per thread.
// ---------------------------------------------------------------------------
#define IN4 (BB * SS * DD / 4)
#define W4  (HH * DD / 4)
#define TOT4 (3 * IN4 + 4 * W4)
__global__ void __launch_bounds__(256) cvt_all(const float4* __restrict__ k,
                                               const float4* __restrict__ q,
                                               const float4* __restrict__ v,
                                               const float4* __restrict__ wk,
                                               const float4* __restrict__ wq,
                                               const float4* __restrict__ wv,
                                               const float4* __restrict__ wo)
{
#pragma unroll
    for (int e = 0; e < 2; e++) {
        int idx = (blockIdx.x * 2 + e) * 256 + threadIdx.x;
        const float4* src;
        __half2* dst;
        int li;
        if (idx < 3 * IN4) {
            int which = idx / IN4;
            li = idx - which * IN4;
            src = (which == 0) ? k : (which == 1) ? q : v;
            dst = (__half2*)g_A16[which];
        } else {
            int r = idx - 3 * IN4;
            int which = r / W4;
            li = r - which * W4;
            src = (which == 0) ? wk : (which == 1) ? wq : (which == 2) ? wv : wo;
            dst = (__half2*)g_W16[which];
        }
        float4 val = src[li];
        dst[li * 2]     = __floats2half2_rn(val.x, val.y);
        dst[li * 2 + 1] = __floats2half2_rn(val.z, val.w);
    }
}

// ---------------------------------------------------------------------------
// Fused projection GEMM (K, Q, V; which = blockIdx.z). BM=128 BN=128 BK=32.
// ---------------------------------------------------------------------------
__global__ void __launch_bounds__(256) proj_fused(const float* __restrict__ bk,
                                                  const float* __restrict__ bq,
                                                  const float* __restrict__ bv) {
    const int which = blockIdx.z;
    const __half* A = g_A16[which];
    const __half* W = g_W16[which];
    __half* out = (which == 0) ? g_Kh : (which == 1) ? g_Qh : g_Vh;
    const float* bias = (which == 0) ? bk : (which == 1) ? bq : bv;

    __shared__ union {
        __half t[3][2][128][40];
        __half C[128][136];
    } sh;

    const int tid = threadIdx.x;
    const int bm = blockIdx.y * 128, bn = blockIdx.x * 128;
    const int w = tid >> 5, l = tid & 31;
    const int wm = w >> 2, wn = w & 3;

    const int c0 = tid, c1 = tid + 256;
    const int ar0 = c0 >> 2, as0 = (c0 & 3) * 8;
    const int ar1 = c1 >> 2, as1 = (c1 & 3) * 8;

    const unsigned sBase = sptr(&sh.t[0][0][0][0]);
    const unsigned stgStride = 2 * 128 * 40 * 2;
    const unsigned bOff = 128 * 40 * 2;

    auto issue = [&](int kb, int st) {
        const __half* Ag = A + (size_t)bm * DD + kb * 32;
        const __half* Bg = W + (size_t)bn * DD + kb * 32;
        unsigned s = sBase + st * stgStride;
        cpa16(s + (unsigned)(ar0 * 40 + as0) * 2, Ag + (size_t)ar0 * DD + as0);
        cpa16(s + (unsigned)(ar1 * 40 + as1) * 2, Ag + (size_t)ar1 * DD + as1);
        cpa16(s + bOff + (unsigned)(ar0 * 40 + as0) * 2, Bg + (size_t)ar0 * DD + as0);
        cpa16(s + bOff + (unsigned)(ar1 * 40 + as1) * 2, Bg + (size_t)ar1 * DD + as1);
        cpa_commit();
    };

    float acc[4][4][4];
#pragma unroll
    for (int mt = 0; mt < 4; mt++)
#pragma unroll
        for (int nt = 0; nt < 4; nt++)
#pragma unroll
            for (int r = 0; r < 4; r++) acc[mt][nt][r] = 0.f;

    const int a_r = l & 15, a_c = (l >> 4) * 8;
    const int b_r = (l & 7) | ((l >> 1) & 8), b_c = l & 8;

    issue(0, 0);
    issue(1, 1);

    const int NKB = DD / 32;
    for (int kb = 0; kb < NKB; kb++) {
        const int st = kb % 3;
        if (kb == NKB - 1) cpa_wait<0>(); else cpa_wait<1>();
        __syncthreads();
        if (kb + 2 < NKB) issue(kb + 2, (kb + 2) % 3);

        const unsigned sA = sBase + st * stgStride;
        const unsigned sB = sA + bOff;
#pragma unroll
        for (int ks = 0; ks < 2; ks++) {
            unsigned a[4][4], bfr[2][4];
#pragma unroll
            for (int mt = 0; mt < 4; mt++) {
                int r = wm * 64 + mt * 16 + a_r;
                int c = ks * 16 + a_c;
                ldsm4(a[mt][0], a[mt][1], a[mt][2], a[mt][3],
                      sA + (unsigned)(r * 40 + c) * 2);
            }
#pragma unroll
            for (int np = 0; np < 2; np++) {
                int r = wn * 32 + np * 16 + b_r;
                int c = ks * 16 + b_c;
                ldsm4(bfr[np][0], bfr[np][1], bfr[np][2], bfr[np][3],
                      sB + (unsigned)(r * 40 + c) * 2);
            }
#pragma unroll
            for (int mt = 0; mt < 4; mt++)
#pragma unroll
                for (int nt = 0; nt < 4; nt++)
                    mma16816(acc[mt][nt], a[mt][0], a[mt][1], a[mt][2], a[mt][3],
                             bfr[nt >> 1][(nt & 1) * 2], bfr[nt >> 1][(nt & 1) * 2 + 1]);
        }
    }
    __syncthreads();

#pragma unroll
    for (int nt = 0; nt < 4; nt++) {
        int c0v = wn * 32 + nt * 8 + 2 * (l & 3);
        float bv0 = bias[bn + c0v], bv1 = bias[bn + c0v + 1];
#pragma unroll
        for (int mt = 0; mt < 4; mt++) {
            int r0 = wm * 64 + mt * 16 + (l >> 2);
            *(__half2*)&sh.C[r0][c0v]     = __floats2half2_rn(acc[mt][nt][0] + bv0, acc[mt][nt][1] + bv1);
            *(__half2*)&sh.C[r0 + 8][c0v] = __floats2half2_rn(acc[mt][nt][2] + bv0, acc[mt][nt][3] + bv1);
        }
    }
    __syncthreads();

    const int h = tid & 15, sg = tid >> 4;
#pragma unroll
    for (int sl = 0; sl < 8; sl++) {
        int s = sg * 8 + sl;
        int m = bm + s;
        int b_ = m >> 11, sloc = m & 2047;
        __half tmp[8];
#pragma unroll
        for (int dd = 0; dd < 8; dd++) tmp[dd] = sh.C[s][h + 16 * dd];
        *(uint4*)&out[(((size_t)(b_ * NHH + h)) * SS + sloc) * DHH + (bn >> 4)] = *(uint4*)tmp;
    }
}

// ---------------------------------------------------------------------------
// FULLY FUSED attention v3: 2 CTAs/SM for pipe overlap (tensor vs MUFU/bars).
// CTA = (16-query k-tile, batch), 512 threads, warp = head. K and V share ONE
// smem buffer (time-multiplexed): K[c] scored -> V[c] loaded under softmax ->
// AV -> K[c+1] issued after AV.
// smem (halves): Q[16][16][72]=18432 | KV[16][16][72]=18432 | S[16][16][24]=6144
// total 43008 halves = 86016 B -> 2 CTAs/SM.
// ---------------------------------------------------------------------------
#define ICH 16
#define NIT (SS / ICH)
__global__ void __launch_bounds__(512, 2) attn_fused() {
    extern __shared__ __half sm[];
    __half* Qs = sm;                        // 18432 halves
    __half* KVs = sm + 18432;               // 18432
    __half* Ss = sm + 2 * 18432;            // 6144

    const int b = blockIdx.y;
    const int kbase = blockIdx.x * 16;
    const int tid = threadIdx.x;
    const int h = tid >> 5;                 // warp = head
    const int l = tid & 31;

    const unsigned sQ = sptr(Qs);
    const unsigned sKV = sptr(KVs);
    const unsigned sS = sptr(Ss);

    const int a_r = l & 15, a_c = (l >> 4) * 8;
    const int b_r = (l & 7) | ((l >> 1) & 8), b_c = l & 8;
    const int bt_r = (l & 7) + ((l >> 3) & 1) * 8;
    const int bt_c = ((l >> 4) & 1) * 8;

    const __half* Kg = g_Kh + (size_t)(b * NHH) * SS * DHH;
    const __half* Qg = g_Qh + (size_t)(b * NHH) * SS * DHH;
    const __half* Vg = g_Vh + (size_t)(b * NHH) * SS * DHH;

    // chunk loader into KV: 256 rows (h*16 + i_local), 8 segs/row, 4 cpa/thread
    auto loadChunk = [&](const __half* src, int ig0) {
#pragma unroll
        for (int t = 0; t < 4; t++) {
            int id = tid + t * 512;
            int row = id >> 3;
            int seg = (id & 7) * 8;
            int h2 = row >> 4, il = row & 15;
            cpa16(sKV + (unsigned)(row * 72 + seg) * 2,
                  src + ((size_t)h2 * SS + ig0 + il) * DHH + seg);
        }
        cpa_commit();
    };

    // prologue: Q (256 rows = h*16 + k_local, 4 cpa/thread) + K chunk 0
#pragma unroll
    for (int t = 0; t < 4; t++) {
        int id = tid + t * 512;
        int row = id >> 3;
        int seg = (id & 7) * 8;
        int h2 = row >> 4, kl = row & 15;
        cpa16(sQ + (unsigned)(row * 72 + seg) * 2,
              Qg + ((size_t)h2 * SS + kbase + kl) * DHH + seg);
    }
    cpa_commit();
    loadChunk(Kg, 0);

    float oacc[8][4];
#pragma unroll
    for (int nt = 0; nt < 8; nt++)
#pragma unroll
        for (int r = 0; r < 4; r++) oacc[nt][r] = 0.f;

    for (int c = 0; c < NIT; c++) {
        // ---- top: K[c] (and on c==0 also Q) must be complete & visible ----
        cpa_wait<0>();
        __syncthreads();

        // ---- phase A: score mma on KV=K[c] ----
        float sacc[2][4];
#pragma unroll
        for (int nt = 0; nt < 2; nt++)
#pragma unroll
            for (int r = 0; r < 4; r++) sacc[nt][r] = 0.f;

#pragma unroll
        for (int ks = 0; ks < 4; ks++) {
            unsigned bk4[4], aq[4];
            ldsm4(bk4[0], bk4[1], bk4[2], bk4[3],
                  sKV + (unsigned)((h * ICH + b_r) * 72 + ks * 16 + b_c) * 2);
            ldsm4(aq[0], aq[1], aq[2], aq[3],
                  sQ + (unsigned)((h * 16 + a_r) * 72 + ks * 16 + a_c) * 2);
            mma16816(sacc[0], aq[0], aq[1], aq[2], aq[3], bk4[0], bk4[1]);
            mma16816(sacc[1], aq[0], aq[1], aq[2], aq[3], bk4[2], bk4[3]);
        }
        // write scaled scores to S[h][k 16][i 24-pad]
#pragma unroll
        for (int nt = 0; nt < 2; nt++) {
            int r = l >> 2;
            int cc = nt * 8 + 2 * (l & 3);
            *(__half2*)&Ss[(h * 16 + r) * 24 + cc] =
                __floats2half2_rn(sacc[nt][0] * 0.125f, sacc[nt][1] * 0.125f);
            *(__half2*)&Ss[(h * 16 + r + 8) * 24 + cc] =
                __floats2half2_rn(sacc[nt][2] * 0.125f, sacc[nt][3] * 0.125f);
        }
        __syncthreads();   // S visible; all K reads done -> KV reusable

        // ---- issue V[c] into KV (covered by softmax) ----
        loadChunk(Vg, c * ICH);

        // ---- phase S: softmax over heads at each (k,i): 16k x 16i = 256 pts
        if (tid < 256) {
            int kq = tid >> 4, iq = tid & 15;
            float v[NHH];
            float mx = -1e30f;
#pragma unroll
            for (int h2 = 0; h2 < NHH; h2++) {
                v[h2] = __half2float(Ss[(h2 * 16 + kq) * 24 + iq]);
                mx = fmaxf(mx, v[h2]);
            }
            float sum = 0.f;
#pragma unroll
            for (int h2 = 0; h2 < NHH; h2++) {
                v[h2] = __expf(v[h2] - mx);
                sum += v[h2];
            }
            float inv = 1.f / sum;
#pragma unroll
            for (int h2 = 0; h2 < NHH; h2++)
                Ss[(h2 * 16 + kq) * 24 + iq] = __float2half_rn(v[h2] * inv);
        }
        cpa_wait<0>();     // V[c] landed
        __syncthreads();   // softmax done + V visible

        // ---- phase B: AV mma on KV=V[c] ----
        {
            unsigned as4[4], bv[4][4];
            ldsm4(as4[0], as4[1], as4[2], as4[3],
                  sS + (unsigned)((h * 16 + a_r) * 24 + a_c) * 2);
#pragma unroll
            for (int np = 0; np < 4; np++)
                ldsm4t(bv[np][0], bv[np][1], bv[np][2], bv[np][3],
                       sKV + (unsigned)((h * ICH + bt_r) * 72 + np * 16 + bt_c) * 2);
#pragma unroll
            for (int nt = 0; nt < 8; nt++)
                mma16816(oacc[nt], as4[0], as4[1], as4[2], as4[3],
                         bv[nt >> 1][(nt & 1) * 2], bv[nt >> 1][(nt & 1) * 2 + 1]);
        }
        __syncthreads();   // all V reads done -> KV reusable for K[c+1]

        // ---- issue K[c+1] ----
        if (c + 1 < NIT) loadChunk(Kg, (c + 1) * ICH);
    }

    // ---- epilogue: Xt[b][16j+h][k] ----
    __half* Xb = g_Xt + (size_t)b * HH * SS;
    {
        int m0 = kbase + (l >> 2);
#pragma unroll
        for (int nt = 0; nt < 8; nt++) {
            int j0 = nt * 8 + 2 * (l & 3);
            Xb[(size_t)(16 * j0 + h) * SS + m0]           = __float2half_rn(oacc[nt][0]);
            Xb[(size_t)(16 * (j0 + 1) + h) * SS + m0]     = __float2half_rn(oacc[nt][1]);
            Xb[(size_t)(16 * j0 + h) * SS + m0 + 8]       = __float2half_rn(oacc[nt][2]);
            Xb[(size_t)(16 * (j0 + 1) + h) * SS + m0 + 8] = __float2half_rn(oacc[nt][3]);
        }
    }
}

// ---------------------------------------------------------------------------
// Output projection v2: out = X @ Wo^T + bias, 3-stage cp.async.
// BM=64 BN=128 BK=32; A read from Xt (channel-major) via trans ldmatrix.
// ---------------------------------------------------------------------------
__global__ void __launch_bounds__(256) outproj_gemm(const float* __restrict__ bias,
                                                    float* __restrict__ out) {
    const __half* Wo = g_W16[3];

    __shared__ __half At[3][32][72];
    __shared__ __half Bt[3][128][40];

    const int tid = threadIdx.x;
    const int bm = blockIdx.y * 64, bn = blockIdx.x * 128;
    const int b_ = bm >> 11, sbase = bm & 2047;
    const int w = tid >> 5, l = tid & 31;
    const int wm = w >> 2, wn = w & 3;

    const int arow = tid >> 3, aseg = (tid & 7) * 8;
    const int bc0 = tid, bc1 = tid + 256;
    const int br0 = bc0 >> 2, bs0 = (bc0 & 3) * 8;
    const int br1 = bc1 >> 2, bs1 = (bc1 & 3) * 8;

    const int at_r = (l & 7) + ((l >> 4) & 1) * 8;
    const int at_c = ((l >> 3) & 1) * 8;
    const int b_r = (l & 7) | ((l >> 1) & 8), b_c = l & 8;

    const unsigned sAt = sptr(&At[0][0][0]);
    const unsigned sBt = sptr(&Bt[0][0][0]);
    const unsigned Abs = 32 * 72 * 2, Bbs = 128 * 40 * 2;

    const __half* Abase = g_Xt + (size_t)b_ * HH * SS + sbase;

    auto issue = [&](int kb, int st) {
        cpa16(sAt + st * Abs + (unsigned)(arow * 72 + aseg) * 2,
              Abase + (size_t)(kb * 32 + arow) * SS + aseg);
        cpa16(sBt + st * Bbs + (unsigned)(br0 * 40 + bs0) * 2,
              Wo + (size_t)(bn + br0) * HH + kb * 32 + bs0);
        cpa16(sBt + st * Bbs + (unsigned)(br1 * 40 + bs1) * 2,
              Wo + (size_t)(bn + br1) * HH + kb * 32 + bs1);
        cpa_commit();
    };

    float acc[2][4][4];
#pragma unroll
    for (int mt = 0; mt < 2; mt++)
#pragma unroll
        for (int nt = 0; nt < 4; nt++)
#pragma unroll
            for (int r = 0; r < 4; r++) acc[mt][nt][r] = 0.f;

    issue(0, 0);
    issue(1, 1);

    const int NKB = HH / 32;
    for (int kb = 0; kb < NKB; kb++) {
        const int st = kb % 3;
        if (kb == NKB - 1) cpa_wait<0>(); else cpa_wait<1>();
        __syncthreads();
        if (kb + 2 < NKB) issue(kb + 2, (kb + 2) % 3);

#pragma unroll
        for (int ks = 0; ks < 2; ks++) {
            unsigned a[2][4], bfr[2][4];
#pragma unroll
            for (int mt = 0; mt < 2; mt++) {
                int r = ks * 16 + at_r;
                int c = wm * 32 + mt * 16 + at_c;
                ldsm4t(a[mt][0], a[mt][1], a[mt][2], a[mt][3],
                       sAt + st * Abs + (unsigned)(r * 72 + c) * 2);
            }
#pragma unroll
            for (int np = 0; np < 2; np++) {
                int r = wn * 32 + np * 16 + b_r;
                int c = ks * 16 + b_c;
                ldsm4(bfr[np][0], bfr[np][1], bfr[np][2], bfr[np][3],
                      sBt + st * Bbs + (unsigned)(r * 40 + c) * 2);
            }
#pragma unroll
            for (int mt = 0; mt < 2; mt++)
#pragma unroll
                for (int nt = 0; nt < 4; nt++)
                    mma16816(acc[mt][nt], a[mt][0], a[mt][1], a[mt][2], a[mt][3],
                             bfr[nt >> 1][(nt & 1) * 2], bfr[nt >> 1][(nt & 1) * 2 + 1]);
        }
        __syncthreads();
    }

#pragma unroll
    for (int nt = 0; nt < 4; nt++) {
        int c0 = bn + wn * 32 + nt * 8 + 2 * (l & 3);
        float bv0 = bias[c0], bv1 = bias[c0 + 1];
#pragma unroll
        for (int mt = 0; mt < 2; mt++) {
            int r0 = bm + wm * 32 + mt * 16 + (l >> 2);
            float2 v0 = make_float2(acc[mt][nt][0] + bv0, acc[mt][nt][1] + bv1);
            float2 v1 = make_float2(acc[mt][nt][2] + bv0, acc[mt][nt][3] + bv1);
            *(float2*)&out[(size_t)r0 * HH + c0] = v0;
            *(float2*)&out[(size_t)(r0 + 8) * HH + c0] = v1;
        }
    }
}

// ---------------------------------------------------------------------------
// Launch
// ---------------------------------------------------------------------------
extern "C" void kernel_launch(void* const* d_in, const int* in_sizes, int n_in,
                              void* d_out, int out_size)
{
    const float* KEY   = (const float*)d_in[0];
    const float* VALUE = (const float*)d_in[1];
    const float* QUERY = (const float*)d_in[2];
    const float* Wk_w  = (const float*)d_in[3];
    const float* Wk_b  = (const float*)d_in[4];
    const float* Wq_w  = (const float*)d_in[5];
    const float* Wq_b  = (const float*)d_in[6];
    const float* Wv_w  = (const float*)d_in[7];
    const float* Wv_b  = (const float*)d_in[8];
    const float* Wo_w  = (const float*)d_in[9];
    const float* Wo_b  = (const float*)d_in[10];
    float* out = (float*)d_out;

    const int fsm = (18432 + 18432 + 6144) * 2;   // 86,016 B
    static bool attr_done = false;
    if (!attr_done) {
        cudaFuncSetAttribute(attn_fused, cudaFuncAttributeMaxDynamicSharedMemorySize, fsm);
        attr_done = true;
    }

    cvt_all<<<TOT4 / 512, 256>>>((const float4*)KEY, (const float4*)QUERY,
                                 (const float4*)VALUE, (const float4*)Wk_w,
                                 (const float4*)Wq_w, (const float4*)Wv_w,
                                 (const float4*)Wo_w);

    dim3 pg(HH / 128, (BB * SS) / 128, 3);         // 768 CTAs
    proj_fused<<<pg, 256>>>(Wk_b, Wq_b, Wv_b);

    dim3 fg(SS / 16, BB);                          // (128, 2) = 256 CTAs, 2/SM
    attn_fused<<<fg, 512, fsm>>>();

    dim3 og(HH / 128, (BB * SS) / 64);             // (8, 64)
    outproj_gemm<<<og, 256>>>(Wo_b, out);
}

// round 11
// speedup vs baseline: 1.3024x; 1.3024x over previous
#include <cuda_runtime.h>
#include <cuda_fp16.h>

#define BB  2
#define SS  2048
#define DD  1024
#define HH  1024
#define NHH 16
#define DHH 64

// ---------------------------------------------------------------------------
// Static scratch
// ---------------------------------------------------------------------------
__device__ __half g_A16[3][BB * SS * DD];          // fp16 KEY, QUERY, VALUE
__device__ __half g_W16[4][HH * DD];               // fp16 Wk, Wq, Wv, Wo
__device__ __half g_Kh[BB * NHH * SS * DHH];       // head-split projections
__device__ __half g_Qh[BB * NHH * SS * DHH];
__device__ __half g_Vh[BB * NHH * SS * DHH];
__device__ __half g_Xt[BB * HH * SS];              // X transposed [b][c][s]

// ---------------------------------------------------------------------------
// PTX helpers
// ---------------------------------------------------------------------------
__device__ __forceinline__ unsigned sptr(const void* p) {
    unsigned a;
    asm("{.reg .u64 t; cvta.to.shared.u64 t, %1; cvt.u32.u64 %0, t;}" : "=r"(a) : "l"(p));
    return a;
}
__device__ __forceinline__ void ldsm4(unsigned& r0, unsigned& r1, unsigned& r2, unsigned& r3, unsigned a) {
    asm volatile("ldmatrix.sync.aligned.m8n8.x4.shared.b16 {%0,%1,%2,%3},[%4];\n"
                 : "=r"(r0), "=r"(r1), "=r"(r2), "=r"(r3) : "r"(a));
}
__device__ __forceinline__ void ldsm4t(unsigned& r0, unsigned& r1, unsigned& r2, unsigned& r3, unsigned a) {
    asm volatile("ldmatrix.sync.aligned.m8n8.x4.trans.shared.b16 {%0,%1,%2,%3},[%4];\n"
                 : "=r"(r0), "=r"(r1), "=r"(r2), "=r"(r3) : "r"(a));
}
__device__ __forceinline__ void mma16816(float* c, unsigned a0, unsigned a1, unsigned a2, unsigned a3,
                                         unsigned b0, unsigned b1) {
    asm volatile("mma.sync.aligned.m16n8k16.row.col.f32.f16.f16.f32 "
                 "{%0,%1,%2,%3},{%4,%5,%6,%7},{%8,%9},{%0,%1,%2,%3};\n"
                 : "+f"(c[0]), "+f"(c[1]), "+f"(c[2]), "+f"(c[3])
                 : "r"(a0), "r"(a1), "r"(a2), "r"(a3), "r"(b0), "r"(b1));
}
__device__ __forceinline__ void cpa16(unsigned d, const void* s) {
    asm volatile("cp.async.cg.shared.global [%0],[%1],16;\n" :: "r"(d), "l"(s));
}
__device__ __forceinline__ void cpa_commit() { asm volatile("cp.async.commit_group;\n"); }
template <int N> __device__ __forceinline__ void cpa_wait() {
    asm volatile("cp.async.wait_group %0;\n" :: "n"(N));
}

// ---------------------------------------------------------------------------
// Fused fp32->fp16 conversion, 2 float4 per thread.
// ---------------------------------------------------------------------------
#define IN4 (BB * SS * DD / 4)
#define W4  (HH * DD / 4)
#define TOT4 (3 * IN4 + 4 * W4)
__global__ void __launch_bounds__(256) cvt_all(const float4* __restrict__ k,
                                               const float4* __restrict__ q,
                                               const float4* __restrict__ v,
                                               const float4* __restrict__ wk,
                                               const float4* __restrict__ wq,
                                               const float4* __restrict__ wv,
                                               const float4* __restrict__ wo)
{
#pragma unroll
    for (int e = 0; e < 2; e++) {
        int idx = (blockIdx.x * 2 + e) * 256 + threadIdx.x;
        const float4* src;
        __half2* dst;
        int li;
        if (idx < 3 * IN4) {
            int which = idx / IN4;
            li = idx - which * IN4;
            src = (which == 0) ? k : (which == 1) ? q : v;
            dst = (__half2*)g_A16[which];
        } else {
            int r = idx - 3 * IN4;
            int which = r / W4;
            li = r - which * W4;
            src = (which == 0) ? wk : (which == 1) ? wq : (which == 2) ? wv : wo;
            dst = (__half2*)g_W16[which];
        }
        float4 val = src[li];
        dst[li * 2]     = __floats2half2_rn(val.x, val.y);
        dst[li * 2 + 1] = __floats2half2_rn(val.z, val.w);
    }
}

// ---------------------------------------------------------------------------
// Fused projection GEMM (K, Q, V; which = blockIdx.z). BM=128 BN=128 BK=32.
// ---------------------------------------------------------------------------
__global__ void __launch_bounds__(256) proj_fused(const float* __restrict__ bk,
                                                  const float* __restrict__ bq,
                                                  const float* __restrict__ bv) {
    const int which = blockIdx.z;
    const __half* A = g_A16[which];
    const __half* W = g_W16[which];
    __half* out = (which == 0) ? g_Kh : (which == 1) ? g_Qh : g_Vh;
    const float* bias = (which == 0) ? bk : (which == 1) ? bq : bv;

    __shared__ union {
        __half t[3][2][128][40];
        __half C[128][136];
    } sh;

    const int tid = threadIdx.x;
    const int bm = blockIdx.y * 128, bn = blockIdx.x * 128;
    const int w = tid >> 5, l = tid & 31;
    const int wm = w >> 2, wn = w & 3;

    const int c0 = tid, c1 = tid + 256;
    const int ar0 = c0 >> 2, as0 = (c0 & 3) * 8;
    const int ar1 = c1 >> 2, as1 = (c1 & 3) * 8;

    const unsigned sBase = sptr(&sh.t[0][0][0][0]);
    const unsigned stgStride = 2 * 128 * 40 * 2;
    const unsigned bOff = 128 * 40 * 2;

    auto issue = [&](int kb, int st) {
        const __half* Ag = A + (size_t)bm * DD + kb * 32;
        const __half* Bg = W + (size_t)bn * DD + kb * 32;
        unsigned s = sBase + st * stgStride;
        cpa16(s + (unsigned)(ar0 * 40 + as0) * 2, Ag + (size_t)ar0 * DD + as0);
        cpa16(s + (unsigned)(ar1 * 40 + as1) * 2, Ag + (size_t)ar1 * DD + as1);
        cpa16(s + bOff + (unsigned)(ar0 * 40 + as0) * 2, Bg + (size_t)ar0 * DD + as0);
        cpa16(s + bOff + (unsigned)(ar1 * 40 + as1) * 2, Bg + (size_t)ar1 * DD + as1);
        cpa_commit();
    };

    float acc[4][4][4];
#pragma unroll
    for (int mt = 0; mt < 4; mt++)
#pragma unroll
        for (int nt = 0; nt < 4; nt++)
#pragma unroll
            for (int r = 0; r < 4; r++) acc[mt][nt][r] = 0.f;

    const int a_r = l & 15, a_c = (l >> 4) * 8;
    const int b_r = (l & 7) | ((l >> 1) & 8), b_c = l & 8;

    issue(0, 0);
    issue(1, 1);

    const int NKB = DD / 32;
    for (int kb = 0; kb < NKB; kb++) {
        const int st = kb % 3;
        if (kb == NKB - 1) cpa_wait<0>(); else cpa_wait<1>();
        __syncthreads();
        if (kb + 2 < NKB) issue(kb + 2, (kb + 2) % 3);

        const unsigned sA = sBase + st * stgStride;
        const unsigned sB = sA + bOff;
#pragma unroll
        for (int ks = 0; ks < 2; ks++) {
            unsigned a[4][4], bfr[2][4];
#pragma unroll
            for (int mt = 0; mt < 4; mt++) {
                int r = wm * 64 + mt * 16 + a_r;
                int c = ks * 16 + a_c;
                ldsm4(a[mt][0], a[mt][1], a[mt][2], a[mt][3],
                      sA + (unsigned)(r * 40 + c) * 2);
            }
#pragma unroll
            for (int np = 0; np < 2; np++) {
                int r = wn * 32 + np * 16 + b_r;
                int c = ks * 16 + b_c;
                ldsm4(bfr[np][0], bfr[np][1], bfr[np][2], bfr[np][3],
                      sB + (unsigned)(r * 40 + c) * 2);
            }
#pragma unroll
            for (int mt = 0; mt < 4; mt++)
#pragma unroll
                for (int nt = 0; nt < 4; nt++)
                    mma16816(acc[mt][nt], a[mt][0], a[mt][1], a[mt][2], a[mt][3],
                             bfr[nt >> 1][(nt & 1) * 2], bfr[nt >> 1][(nt & 1) * 2 + 1]);
        }
    }
    __syncthreads();

#pragma unroll
    for (int nt = 0; nt < 4; nt++) {
        int c0v = wn * 32 + nt * 8 + 2 * (l & 3);
        float bv0 = bias[bn + c0v], bv1 = bias[bn + c0v + 1];
#pragma unroll
        for (int mt = 0; mt < 4; mt++) {
            int r0 = wm * 64 + mt * 16 + (l >> 2);
            *(__half2*)&sh.C[r0][c0v]     = __floats2half2_rn(acc[mt][nt][0] + bv0, acc[mt][nt][1] + bv1);
            *(__half2*)&sh.C[r0 + 8][c0v] = __floats2half2_rn(acc[mt][nt][2] + bv0, acc[mt][nt][3] + bv1);
        }
    }
    __syncthreads();

    const int h = tid & 15, sg = tid >> 4;
#pragma unroll
    for (int sl = 0; sl < 8; sl++) {
        int s = sg * 8 + sl;
        int m = bm + s;
        int b_ = m >> 11, sloc = m & 2047;
        __half tmp[8];
#pragma unroll
        for (int dd = 0; dd < 8; dd++) tmp[dd] = sh.C[s][h + 16 * dd];
        *(uint4*)&out[(((size_t)(b_ * NHH + h)) * SS + sloc) * DHH + (bn >> 4)] = *(uint4*)tmp;
    }
}

// ---------------------------------------------------------------------------
// FULLY FUSED attention (R9 v2 structure + coalesced staged epilogue).
// CTA = (32-query k-tile, batch), 512 threads, warp = head. Double-buffered K;
// V[c]+K[c+1] issued together at the top of each iteration, covered by the
// score mma + softmax window. Epilogue stages O into smem [c=16j+h][k] then
// writes Xt with uint4 stores (64B contiguous per channel row).
// smem (halves): Q 36864 | K 2x18432 | V 18432 | S 12288  => 208,896 B.
// Epilogue reuses the same region: Osm[1024][40] = 40,960 halves.
// ---------------------------------------------------------------------------
#define ICH 16
#define NIT (SS / ICH)
__global__ void __launch_bounds__(512, 1) attn_fused() {
    extern __shared__ __half sm[];
    __half* Qs = sm;                        // 36864 halves
    __half* Ks = sm + 36864;                // 2 buffers x 18432
    __half* Vs = sm + 36864 + 2 * 18432;    // 18432
    __half* Ss = sm + 36864 + 3 * 18432;    // 12288

    const int b = blockIdx.y;
    const int kbase = blockIdx.x * 32;
    const int tid = threadIdx.x;
    const int h = tid >> 5;                 // warp = head
    const int l = tid & 31;

    const unsigned sQ = sptr(Qs);
    const unsigned sK = sptr(Ks);
    const unsigned sV = sptr(Vs);
    const unsigned sS = sptr(Ss);
    const unsigned Kbs = 18432 * 2;         // bytes per K buffer

    const int a_r = l & 15, a_c = (l >> 4) * 8;
    const int b_r = (l & 7) | ((l >> 1) & 8), b_c = l & 8;
    const int bt_r = (l & 7) + ((l >> 3) & 1) * 8;
    const int bt_c = ((l >> 4) & 1) * 8;

    const __half* Kg = g_Kh + (size_t)(b * NHH) * SS * DHH;
    const __half* Qg = g_Qh + (size_t)(b * NHH) * SS * DHH;
    const __half* Vg = g_Vh + (size_t)(b * NHH) * SS * DHH;

    // chunk loader: 256 rows (h*16 + i_local), 8 segs/row, 4 cpa/thread.
    // NOTE: no commit inside — caller groups loads.
    auto loadChunk = [&](const __half* src, unsigned dstbase, int ig0) {
#pragma unroll
        for (int t = 0; t < 4; t++) {
            int id = tid + t * 512;
            int row = id >> 3;
            int seg = (id & 7) * 8;
            int h2 = row >> 4, il = row & 15;
            cpa16(dstbase + (unsigned)(row * 72 + seg) * 2,
                  src + ((size_t)h2 * SS + ig0 + il) * DHH + seg);
        }
    };

    // prologue: Q (512 rows, 8 cpa/thread) + K chunk 0, single group
#pragma unroll
    for (int t = 0; t < 8; t++) {
        int id = tid + t * 512;
        int row = id >> 3;
        int seg = (id & 7) * 8;
        int h2 = row >> 5, kl = row & 31;
        cpa16(sQ + (unsigned)(row * 72 + seg) * 2,
              Qg + ((size_t)h2 * SS + kbase + kl) * DHH + seg);
    }
    loadChunk(Kg, sK, 0);
    cpa_commit();
    cpa_wait<0>();
    __syncthreads();

    float oacc[2][8][4];
#pragma unroll
    for (int mt = 0; mt < 2; mt++)
#pragma unroll
        for (int nt = 0; nt < 8; nt++)
#pragma unroll
            for (int r = 0; r < 4; r++) oacc[mt][nt][r] = 0.f;

    for (int c = 0; c < NIT; c++) {
        const unsigned kcur = sK + (unsigned)(c & 1) * Kbs;

        // ---- top: issue V[c] and K[c+1] together (one group) ----
        loadChunk(Vg, sV, c * ICH);
        if (c + 1 < NIT) loadChunk(Kg, sK + (unsigned)((c + 1) & 1) * Kbs, (c + 1) * ICH);
        cpa_commit();

        // ---- phase A: score mma on K[c] ----
        float sacc[2][2][4];
#pragma unroll
        for (int mt = 0; mt < 2; mt++)
#pragma unroll
            for (int nt = 0; nt < 2; nt++)
#pragma unroll
                for (int r = 0; r < 4; r++) sacc[mt][nt][r] = 0.f;

#pragma unroll
        for (int ks = 0; ks < 4; ks++) {
            unsigned bk4[4];
            ldsm4(bk4[0], bk4[1], bk4[2], bk4[3],
                  kcur + (unsigned)((h * ICH + b_r) * 72 + ks * 16 + b_c) * 2);
#pragma unroll
            for (int mt = 0; mt < 2; mt++) {
                unsigned aq[4];
                ldsm4(aq[0], aq[1], aq[2], aq[3],
                      sQ + (unsigned)((h * 32 + mt * 16 + a_r) * 72 + ks * 16 + a_c) * 2);
                mma16816(sacc[mt][0], aq[0], aq[1], aq[2], aq[3], bk4[0], bk4[1]);
                mma16816(sacc[mt][1], aq[0], aq[1], aq[2], aq[3], bk4[2], bk4[3]);
            }
        }
#pragma unroll
        for (int mt = 0; mt < 2; mt++)
#pragma unroll
            for (int nt = 0; nt < 2; nt++) {
                int r = mt * 16 + (l >> 2);
                int cc = nt * 8 + 2 * (l & 3);
                *(__half2*)&Ss[(h * 32 + r) * 24 + cc] =
                    __floats2half2_rn(sacc[mt][nt][0] * 0.125f, sacc[mt][nt][1] * 0.125f);
                *(__half2*)&Ss[(h * 32 + r + 8) * 24 + cc] =
                    __floats2half2_rn(sacc[mt][nt][2] * 0.125f, sacc[mt][nt][3] * 0.125f);
            }
        __syncthreads();   // S visible

        // ---- phase S: softmax over heads at each (k,i) ----
        {
            int kq = tid >> 4, iq = tid & 15;
            float v[NHH];
            float mx = -1e30f;
#pragma unroll
            for (int h2 = 0; h2 < NHH; h2++) {
                v[h2] = __half2float(Ss[(h2 * 32 + kq) * 24 + iq]);
                mx = fmaxf(mx, v[h2]);
            }
            float sum = 0.f;
#pragma unroll
            for (int h2 = 0; h2 < NHH; h2++) {
                v[h2] = __expf(v[h2] - mx);
                sum += v[h2];
            }
            float inv = 1.f / sum;
#pragma unroll
            for (int h2 = 0; h2 < NHH; h2++)
                Ss[(h2 * 32 + kq) * 24 + iq] = __float2half_rn(v[h2] * inv);
        }
        cpa_wait<0>();     // V[c] (+K[c+1]) arrived — covered by A + softmax
        __syncthreads();   // S normalized + V ready

        // ---- phase B: AV mma ----
        unsigned as[2][4], bv[4][4];
#pragma unroll
        for (int mt = 0; mt < 2; mt++)
            ldsm4(as[mt][0], as[mt][1], as[mt][2], as[mt][3],
                  sS + (unsigned)((h * 32 + mt * 16 + a_r) * 24 + a_c) * 2);
#pragma unroll
        for (int np = 0; np < 4; np++)
            ldsm4t(bv[np][0], bv[np][1], bv[np][2], bv[np][3],
                   sV + (unsigned)((h * ICH + bt_r) * 72 + np * 16 + bt_c) * 2);
#pragma unroll
        for (int mt = 0; mt < 2; mt++)
#pragma unroll
            for (int nt = 0; nt < 8; nt++)
                mma16816(oacc[mt][nt], as[mt][0], as[mt][1], as[mt][2], as[mt][3],
                         bv[nt >> 1][(nt & 1) * 2], bv[nt >> 1][(nt & 1) * 2 + 1]);

        __syncthreads();   // V/S free for next iteration's overwrites
    }

    // ---- epilogue: stage O to smem [c=16j+h][k stride 40], then uint4 out ----
    __half* Osm = sm;   // 1024 x 40 halves = 40960 <= 104448 available
#pragma unroll
    for (int mt = 0; mt < 2; mt++) {
        int k0 = mt * 16 + (l >> 2);
#pragma unroll
        for (int nt = 0; nt < 8; nt++) {
            int j0 = nt * 8 + 2 * (l & 3);
            Osm[(16 * j0 + h) * 40 + k0]           = __float2half_rn(oacc[mt][nt][0]);
            Osm[(16 * (j0 + 1) + h) * 40 + k0]     = __float2half_rn(oacc[mt][nt][1]);
            Osm[(16 * j0 + h) * 40 + k0 + 8]       = __float2half_rn(oacc[mt][nt][2]);
            Osm[(16 * (j0 + 1) + h) * 40 + k0 + 8] = __float2half_rn(oacc[mt][nt][3]);
        }
    }
    __syncthreads();

    __half* Xb = g_Xt + (size_t)b * HH * SS;
#pragma unroll
    for (int e = 0; e < 8; e++) {
        int id = e * 512 + tid;            // 0..4095
        int kseg = (id & 3) * 8;           // 0,8,16,24
        int cc = id >> 2;                  // channel 0..1023  (c = 16j+h)
        uint4 val = *(const uint4*)&Osm[cc * 40 + kseg];
        *(uint4*)&Xb[(size_t)cc * SS + kbase + kseg] = val;
    }
}

// ---------------------------------------------------------------------------
// Output projection v2: out = X @ Wo^T + bias, 3-stage cp.async.
// BM=64 BN=128 BK=32; A read from Xt (channel-major) via trans ldmatrix.
// ---------------------------------------------------------------------------
__global__ void __launch_bounds__(256) outproj_gemm(const float* __restrict__ bias,
                                                    float* __restrict__ out) {
    const __half* Wo = g_W16[3];

    __shared__ __half At[3][32][72];
    __shared__ __half Bt[3][128][40];

    const int tid = threadIdx.x;
    const int bm = blockIdx.y * 64, bn = blockIdx.x * 128;
    const int b_ = bm >> 11, sbase = bm & 2047;
    const int w = tid >> 5, l = tid & 31;
    const int wm = w >> 2, wn = w & 3;

    const int arow = tid >> 3, aseg = (tid & 7) * 8;
    const int bc0 = tid, bc1 = tid + 256;
    const int br0 = bc0 >> 2, bs0 = (bc0 & 3) * 8;
    const int br1 = bc1 >> 2, bs1 = (bc1 & 3) * 8;

    const int at_r = (l & 7) + ((l >> 4) & 1) * 8;
    const int at_c = ((l >> 3) & 1) * 8;
    const int b_r = (l & 7) | ((l >> 1) & 8), b_c = l & 8;

    const unsigned sAt = sptr(&At[0][0][0]);
    const unsigned sBt = sptr(&Bt[0][0][0]);
    const unsigned Abs = 32 * 72 * 2, Bbs = 128 * 40 * 2;

    const __half* Abase = g_Xt + (size_t)b_ * HH * SS + sbase;

    auto issue = [&](int kb, int st) {
        cpa16(sAt + st * Abs + (unsigned)(arow * 72 + aseg) * 2,
              Abase + (size_t)(kb * 32 + arow) * SS + aseg);
        cpa16(sBt + st * Bbs + (unsigned)(br0 * 40 + bs0) * 2,
              Wo + (size_t)(bn + br0) * HH + kb * 32 + bs0);
        cpa16(sBt + st * Bbs + (unsigned)(br1 * 40 + bs1) * 2,
              Wo + (size_t)(bn + br1) * HH + kb * 32 + bs1);
        cpa_commit();
    };

    float acc[2][4][4];
#pragma unroll
    for (int mt = 0; mt < 2; mt++)
#pragma unroll
        for (int nt = 0; nt < 4; nt++)
#pragma unroll
            for (int r = 0; r < 4; r++) acc[mt][nt][r] = 0.f;

    issue(0, 0);
    issue(1, 1);

    const int NKB = HH / 32;
    for (int kb = 0; kb < NKB; kb++) {
        const int st = kb % 3;
        if (kb == NKB - 1) cpa_wait<0>(); else cpa_wait<1>();
        __syncthreads();
        if (kb + 2 < NKB) issue(kb + 2, (kb + 2) % 3);

#pragma unroll
        for (int ks = 0; ks < 2; ks++) {
            unsigned a[2][4], bfr[2][4];
#pragma unroll
            for (int mt = 0; mt < 2; mt++) {
                int r = ks * 16 + at_r;
                int c = wm * 32 + mt * 16 + at_c;
                ldsm4t(a[mt][0], a[mt][1], a[mt][2], a[mt][3],
                       sAt + st * Abs + (unsigned)(r * 72 + c) * 2);
            }
#pragma unroll
            for (int np = 0; np < 2; np++) {
                int r = wn * 32 + np * 16 + b_r;
                int c = ks * 16 + b_c;
                ldsm4(bfr[np][0], bfr[np][1], bfr[np][2], bfr[np][3],
                      sBt + st * Bbs + (unsigned)(r * 40 + c) * 2);
            }
#pragma unroll
            for (int mt = 0; mt < 2; mt++)
#pragma unroll
                for (int nt = 0; nt < 4; nt++)
                    mma16816(acc[mt][nt], a[mt][0], a[mt][1], a[mt][2], a[mt][3],
                             bfr[nt >> 1][(nt & 1) * 2], bfr[nt >> 1][(nt & 1) * 2 + 1]);
        }
        __syncthreads();
    }

#pragma unroll
    for (int nt = 0; nt < 4; nt++) {
        int c0 = bn + wn * 32 + nt * 8 + 2 * (l & 3);
        float bv0 = bias[c0], bv1 = bias[c0 + 1];
#pragma unroll
        for (int mt = 0; mt < 2; mt++) {
            int r0 = bm + wm * 32 + mt * 16 + (l >> 2);
            float2 v0 = make_float2(acc[mt][nt][0] + bv0, acc[mt][nt][1] + bv1);
            float2 v1 = make_float2(acc[mt][nt][2] + bv0, acc[mt][nt][3] + bv1);
            *(float2*)&out[(size_t)r0 * HH + c0] = v0;
            *(float2*)&out[(size_t)(r0 + 8) * HH + c0] = v1;
        }
    }
}

// ---------------------------------------------------------------------------
// Launch
// ---------------------------------------------------------------------------
extern "C" void kernel_launch(void* const* d_in, const int* in_sizes, int n_in,
                              void* d_out, int out_size)
{
    const float* KEY   = (const float*)d_in[0];
    const float* VALUE = (const float*)d_in[1];
    const float* QUERY = (const float*)d_in[2];
    const float* Wk_w  = (const float*)d_in[3];
    const float* Wk_b  = (const float*)d_in[4];
    const float* Wq_w  = (const float*)d_in[5];
    const float* Wq_b  = (const float*)d_in[6];
    const float* Wv_w  = (const float*)d_in[7];
    const float* Wv_b  = (const float*)d_in[8];
    const float* Wo_w  = (const float*)d_in[9];
    const float* Wo_b  = (const float*)d_in[10];
    float* out = (float*)d_out;

    const int fsm = (36864 + 2 * 18432 + 18432 + 12288) * 2;   // 208,896 B
    static bool attr_done = false;
    if (!attr_done) {
        cudaFuncSetAttribute(attn_fused, cudaFuncAttributeMaxDynamicSharedMemorySize, fsm);
        attr_done = true;
    }

    cvt_all<<<TOT4 / 512, 256>>>((const float4*)KEY, (const float4*)QUERY,
                                 (const float4*)VALUE, (const float4*)Wk_w,
                                 (const float4*)Wq_w, (const float4*)Wv_w,
                                 (const float4*)Wo_w);

    dim3 pg(HH / 128, (BB * SS) / 128, 3);         // 768 CTAs
    proj_fused<<<pg, 256>>>(Wk_b, Wq_b, Wv_b);

    dim3 fg(SS / 32, BB);                          // (64, 2) = 128 CTAs
    attn_fused<<<fg, 512, fsm>>>();

    dim3 og(HH / 128, (BB * SS) / 64);             // (8, 64)
    outproj_gemm<<<og, 256>>>(Wo_b, out);
}

// round 12
// speedup vs baseline: 1.3107x; 1.0064x over previous
#include <cuda_runtime.h>
#include <cuda_fp16.h>

#define BB  2
#define SS  2048
#define DD  1024
#define HH  1024
#define NHH 16
#define DHH 64

// ---------------------------------------------------------------------------
// Static scratch
// ---------------------------------------------------------------------------
__device__ __half g_A16[3][BB * SS * DD];          // fp16 KEY, QUERY, VALUE
__device__ __half g_W16[4][HH * DD];               // fp16 Wk, Wq, Wv, Wo
__device__ __half g_Kh[BB * NHH * SS * DHH];       // head-split projections
__device__ __half g_Qh[BB * NHH * SS * DHH];
__device__ __half g_Vh[BB * NHH * SS * DHH];
__device__ __half g_Xt[BB * HH * SS];              // X transposed [b][c][s]

// ---------------------------------------------------------------------------
// PTX helpers
// ---------------------------------------------------------------------------
__device__ __forceinline__ unsigned sptr(const void* p) {
    unsigned a;
    asm("{.reg .u64 t; cvta.to.shared.u64 t, %1; cvt.u32.u64 %0, t;}" : "=r"(a) : "l"(p));
    return a;
}
__device__ __forceinline__ void ldsm4(unsigned& r0, unsigned& r1, unsigned& r2, unsigned& r3, unsigned a) {
    asm volatile("ldmatrix.sync.aligned.m8n8.x4.shared.b16 {%0,%1,%2,%3},[%4];\n"
                 : "=r"(r0), "=r"(r1), "=r"(r2), "=r"(r3) : "r"(a));
}
__device__ __forceinline__ void ldsm4t(unsigned& r0, unsigned& r1, unsigned& r2, unsigned& r3, unsigned a) {
    asm volatile("ldmatrix.sync.aligned.m8n8.x4.trans.shared.b16 {%0,%1,%2,%3},[%4];\n"
                 : "=r"(r0), "=r"(r1), "=r"(r2), "=r"(r3) : "r"(a));
}
__device__ __forceinline__ void mma16816(float* c, unsigned a0, unsigned a1, unsigned a2, unsigned a3,
                                         unsigned b0, unsigned b1) {
    asm volatile("mma.sync.aligned.m16n8k16.row.col.f32.f16.f16.f32 "
                 "{%0,%1,%2,%3},{%4,%5,%6,%7},{%8,%9},{%0,%1,%2,%3};\n"
                 : "+f"(c[0]), "+f"(c[1]), "+f"(c[2]), "+f"(c[3])
                 : "r"(a0), "r"(a1), "r"(a2), "r"(a3), "r"(b0), "r"(b1));
}
__device__ __forceinline__ void cpa16(unsigned d, const void* s) {
    asm volatile("cp.async.cg.shared.global [%0],[%1],16;\n" :: "r"(d), "l"(s));
}
__device__ __forceinline__ void cpa_commit() { asm volatile("cp.async.commit_group;\n"); }
template <int N> __device__ __forceinline__ void cpa_wait() {
    asm volatile("cp.async.wait_group %0;\n" :: "n"(N));
}

// ---------------------------------------------------------------------------
// Fused fp32->fp16 conversion, 2 float4 per thread.
// ---------------------------------------------------------------------------
#define IN4 (BB * SS * DD / 4)
#define W4  (HH * DD / 4)
#define TOT4 (3 * IN4 + 4 * W4)
__global__ void __launch_bounds__(256) cvt_all(const float4* __restrict__ k,
                                               const float4* __restrict__ q,
                                               const float4* __restrict__ v,
                                               const float4* __restrict__ wk,
                                               const float4* __restrict__ wq,
                                               const float4* __restrict__ wv,
                                               const float4* __restrict__ wo)
{
#pragma unroll
    for (int e = 0; e < 2; e++) {
        int idx = (blockIdx.x * 2 + e) * 256 + threadIdx.x;
        const float4* src;
        __half2* dst;
        int li;
        if (idx < 3 * IN4) {
            int which = idx / IN4;
            li = idx - which * IN4;
            src = (which == 0) ? k : (which == 1) ? q : v;
            dst = (__half2*)g_A16[which];
        } else {
            int r = idx - 3 * IN4;
            int which = r / W4;
            li = r - which * W4;
            src = (which == 0) ? wk : (which == 1) ? wq : (which == 2) ? wv : wo;
            dst = (__half2*)g_W16[which];
        }
        float4 val = src[li];
        dst[li * 2]     = __floats2half2_rn(val.x, val.y);
        dst[li * 2 + 1] = __floats2half2_rn(val.z, val.w);
    }
}

// ---------------------------------------------------------------------------
// Fused projection GEMM (K, Q, V; which = blockIdx.z). BM=128 BN=128 BK=32.
// ---------------------------------------------------------------------------
__global__ void __launch_bounds__(256) proj_fused(const float* __restrict__ bk,
                                                  const float* __restrict__ bq,
                                                  const float* __restrict__ bv) {
    const int which = blockIdx.z;
    const __half* A = g_A16[which];
    const __half* W = g_W16[which];
    __half* out = (which == 0) ? g_Kh : (which == 1) ? g_Qh : g_Vh;
    const float* bias = (which == 0) ? bk : (which == 1) ? bq : bv;

    __shared__ union {
        __half t[3][2][128][40];
        __half C[128][136];
    } sh;

    const int tid = threadIdx.x;
    const int bm = blockIdx.y * 128, bn = blockIdx.x * 128;
    const int w = tid >> 5, l = tid & 31;
    const int wm = w >> 2, wn = w & 3;

    const int c0 = tid, c1 = tid + 256;
    const int ar0 = c0 >> 2, as0 = (c0 & 3) * 8;
    const int ar1 = c1 >> 2, as1 = (c1 & 3) * 8;

    const unsigned sBase = sptr(&sh.t[0][0][0][0]);
    const unsigned stgStride = 2 * 128 * 40 * 2;
    const unsigned bOff = 128 * 40 * 2;

    auto issue = [&](int kb, int st) {
        const __half* Ag = A + (size_t)bm * DD + kb * 32;
        const __half* Bg = W + (size_t)bn * DD + kb * 32;
        unsigned s = sBase + st * stgStride;
        cpa16(s + (unsigned)(ar0 * 40 + as0) * 2, Ag + (size_t)ar0 * DD + as0);
        cpa16(s + (unsigned)(ar1 * 40 + as1) * 2, Ag + (size_t)ar1 * DD + as1);
        cpa16(s + bOff + (unsigned)(ar0 * 40 + as0) * 2, Bg + (size_t)ar0 * DD + as0);
        cpa16(s + bOff + (unsigned)(ar1 * 40 + as1) * 2, Bg + (size_t)ar1 * DD + as1);
        cpa_commit();
    };

    float acc[4][4][4];
#pragma unroll
    for (int mt = 0; mt < 4; mt++)
#pragma unroll
        for (int nt = 0; nt < 4; nt++)
#pragma unroll
            for (int r = 0; r < 4; r++) acc[mt][nt][r] = 0.f;

    const int a_r = l & 15, a_c = (l >> 4) * 8;
    const int b_r = (l & 7) | ((l >> 1) & 8), b_c = l & 8;

    issue(0, 0);
    issue(1, 1);

    const int NKB = DD / 32;
    for (int kb = 0; kb < NKB; kb++) {
        const int st = kb % 3;
        if (kb == NKB - 1) cpa_wait<0>(); else cpa_wait<1>();
        __syncthreads();
        if (kb + 2 < NKB) issue(kb + 2, (kb + 2) % 3);

        const unsigned sA = sBase + st * stgStride;
        const unsigned sB = sA + bOff;
#pragma unroll
        for (int ks = 0; ks < 2; ks++) {
            unsigned a[4][4], bfr[2][4];
#pragma unroll
            for (int mt = 0; mt < 4; mt++) {
                int r = wm * 64 + mt * 16 + a_r;
                int c = ks * 16 + a_c;
                ldsm4(a[mt][0], a[mt][1], a[mt][2], a[mt][3],
                      sA + (unsigned)(r * 40 + c) * 2);
            }
#pragma unroll
            for (int np = 0; np < 2; np++) {
                int r = wn * 32 + np * 16 + b_r;
                int c = ks * 16 + b_c;
                ldsm4(bfr[np][0], bfr[np][1], bfr[np][2], bfr[np][3],
                      sB + (unsigned)(r * 40 + c) * 2);
            }
#pragma unroll
            for (int mt = 0; mt < 4; mt++)
#pragma unroll
                for (int nt = 0; nt < 4; nt++)
                    mma16816(acc[mt][nt], a[mt][0], a[mt][1], a[mt][2], a[mt][3],
                             bfr[nt >> 1][(nt & 1) * 2], bfr[nt >> 1][(nt & 1) * 2 + 1]);
        }
    }
    __syncthreads();

#pragma unroll
    for (int nt = 0; nt < 4; nt++) {
        int c0v = wn * 32 + nt * 8 + 2 * (l & 3);
        float bv0 = bias[bn + c0v], bv1 = bias[bn + c0v + 1];
#pragma unroll
        for (int mt = 0; mt < 4; mt++) {
            int r0 = wm * 64 + mt * 16 + (l >> 2);
            *(__half2*)&sh.C[r0][c0v]     = __floats2half2_rn(acc[mt][nt][0] + bv0, acc[mt][nt][1] + bv1);
            *(__half2*)&sh.C[r0 + 8][c0v] = __floats2half2_rn(acc[mt][nt][2] + bv0, acc[mt][nt][3] + bv1);
        }
    }
    __syncthreads();

    const int h = tid & 15, sg = tid >> 4;
#pragma unroll
    for (int sl = 0; sl < 8; sl++) {
        int s = sg * 8 + sl;
        int m = bm + s;
        int b_ = m >> 11, sloc = m & 2047;
        __half tmp[8];
#pragma unroll
        for (int dd = 0; dd < 8; dd++) tmp[dd] = sh.C[s][h + 16 * dd];
        *(uint4*)&out[(((size_t)(b_ * NHH + h)) * SS + sloc) * DHH + (bn >> 4)] = *(uint4*)tmp;
    }
}

// ---------------------------------------------------------------------------
// FULLY FUSED attention v4: Q in registers; softmax[c-1] fused into score[c]
// phase (MUFU overlaps HMMA in-warp); 2 barriers/iter; exact cp.async ledger.
// smem (halves): QV 36864 (Q prologue, then V ring 2x18432) | K ring 2x18432 |
// S ring 2x12288 (stride 24). Total 98304 halves = 196,608 B, 1 CTA/SM.
// Ledger (commit order): ..., V[c-1]@A(c-1), K[c+1]@B(c-1), [WAIT@A(c)],
// V[c]@A(c), K[c+2]@B(c), ...  wait<1> at A(c) guarantees V[c-1] & K[c] done.
// ---------------------------------------------------------------------------
#define ICH 16
#define NIT (SS / ICH)
__global__ void __launch_bounds__(512, 1) attn_fused() {
    extern __shared__ __half sm[];
    __half* QV = sm;                        // 36864: Q (prologue) -> V ring
    __half* Ss = sm + 36864 + 2 * 18432;    // after K ring: 2 x 12288

    const int b = blockIdx.y;
    const int kbase = blockIdx.x * 32;
    const int tid = threadIdx.x;
    const int h = tid >> 5;                 // warp = head
    const int l = tid & 31;

    const unsigned sQV = sptr(QV);
    const unsigned sK = sQV + 36864u * 2;   // K ring base (bytes)
    const unsigned sS = sK + 2u * 18432 * 2;
    const unsigned Vbs = 18432 * 2;
    const unsigned Kbs = 18432 * 2;
    const unsigned Sbs = 12288 * 2;

    const int a_r = l & 15, a_c = (l >> 4) * 8;
    const int b_r = (l & 7) | ((l >> 1) & 8), b_c = l & 8;
    const int bt_r = (l & 7) + ((l >> 3) & 1) * 8;
    const int bt_c = ((l >> 4) & 1) * 8;

    const __half* Kg = g_Kh + (size_t)(b * NHH) * SS * DHH;
    const __half* Qg = g_Qh + (size_t)(b * NHH) * SS * DHH;
    const __half* Vg = g_Vh + (size_t)(b * NHH) * SS * DHH;

    // chunk loader: 256 rows (h2*16 + i_local), 8 segs/row, 4 cpa/thread + commit
    auto loadChunk = [&](const __half* src, unsigned dstbase, int ig0) {
#pragma unroll
        for (int t = 0; t < 4; t++) {
            int id = tid + t * 512;
            int row = id >> 3;
            int seg = (id & 7) * 8;
            int h2 = row >> 4, il = row & 15;
            cpa16(dstbase + (unsigned)(row * 72 + seg) * 2,
                  src + ((size_t)h2 * SS + ig0 + il) * DHH + seg);
        }
        cpa_commit();
    };

    // ---- prologue: Q (group), K[0] (group), K[1] (group) ----
#pragma unroll
    for (int t = 0; t < 8; t++) {
        int id = tid + t * 512;
        int row = id >> 3;
        int seg = (id & 7) * 8;
        int h2 = row >> 5, kl = row & 31;
        cpa16(sQV + (unsigned)(row * 72 + seg) * 2,
              Qg + ((size_t)h2 * SS + kbase + kl) * DHH + seg);
    }
    cpa_commit();
    loadChunk(Kg, sK, 0);
    loadChunk(Kg, sK + Kbs, ICH);
    cpa_wait<2>();                 // Q done (K0,K1 may be in flight)
    __syncthreads();

    // ---- Q -> registers (A operands for score) ----
    unsigned aq[2][4][4];
#pragma unroll
    for (int mt = 0; mt < 2; mt++)
#pragma unroll
        for (int ks = 0; ks < 4; ks++)
            ldsm4(aq[mt][ks][0], aq[mt][ks][1], aq[mt][ks][2], aq[mt][ks][3],
                  sQV + (unsigned)((h * 32 + mt * 16 + a_r) * 72 + ks * 16 + a_c) * 2);
    __syncthreads();               // Q reads done -> QV region becomes V ring

    float oacc[2][8][4];
#pragma unroll
    for (int mt = 0; mt < 2; mt++)
#pragma unroll
        for (int nt = 0; nt < 8; nt++)
#pragma unroll
            for (int r = 0; r < 4; r++) oacc[mt][nt][r] = 0.f;

    for (int c = 0; c <= NIT; c++) {
        // ---- A-top: wait + barrier, then issue V[c] ----
        if (c < NIT - 1) cpa_wait<1>(); else cpa_wait<0>();
        __syncthreads();
        if (c < NIT) loadChunk(Vg, sQV + (unsigned)(c & 1) * Vbs, c * ICH);

        // ---- A-body: softmax[c-1] (MUFU) fused with score[c] (HMMA) ----
        if (c >= 1) {
            __half* Sp = Ss + ((c - 1) & 1) * 12288;
            int kq = tid >> 4, iq = tid & 15;
            float v[NHH];
            float mx = -1e30f;
#pragma unroll
            for (int h2 = 0; h2 < NHH; h2++) {
                v[h2] = __half2float(Sp[(h2 * 32 + kq) * 24 + iq]);
                mx = fmaxf(mx, v[h2]);
            }
            float sum = 0.f;
#pragma unroll
            for (int h2 = 0; h2 < NHH; h2++) {
                v[h2] = __expf(v[h2] - mx);
                sum += v[h2];
            }
            float inv = 1.f / sum;
#pragma unroll
            for (int h2 = 0; h2 < NHH; h2++)
                Sp[(h2 * 32 + kq) * 24 + iq] = __float2half_rn(v[h2] * inv);
        }
        if (c < NIT) {
            float sacc[2][2][4];
#pragma unroll
            for (int mt = 0; mt < 2; mt++)
#pragma unroll
                for (int nt = 0; nt < 2; nt++)
#pragma unroll
                    for (int r = 0; r < 4; r++) sacc[mt][nt][r] = 0.f;

            const unsigned kcur = sK + (unsigned)(c & 1) * Kbs;
#pragma unroll
            for (int ks = 0; ks < 4; ks++) {
                unsigned bk4[4];
                ldsm4(bk4[0], bk4[1], bk4[2], bk4[3],
                      kcur + (unsigned)((h * ICH + b_r) * 72 + ks * 16 + b_c) * 2);
#pragma unroll
                for (int mt = 0; mt < 2; mt++) {
                    mma16816(sacc[mt][0], aq[mt][ks][0], aq[mt][ks][1], aq[mt][ks][2], aq[mt][ks][3],
                             bk4[0], bk4[1]);
                    mma16816(sacc[mt][1], aq[mt][ks][0], aq[mt][ks][1], aq[mt][ks][2], aq[mt][ks][3],
                             bk4[2], bk4[3]);
                }
            }
            __half* Sw = Ss + (c & 1) * 12288;
#pragma unroll
            for (int mt = 0; mt < 2; mt++)
#pragma unroll
                for (int nt = 0; nt < 2; nt++) {
                    int r = mt * 16 + (l >> 2);
                    int cc = nt * 8 + 2 * (l & 3);
                    *(__half2*)&Sw[(h * 32 + r) * 24 + cc] =
                        __floats2half2_rn(sacc[mt][nt][0] * 0.125f, sacc[mt][nt][1] * 0.125f);
                    *(__half2*)&Sw[(h * 32 + r + 8) * 24 + cc] =
                        __floats2half2_rn(sacc[mt][nt][2] * 0.125f, sacc[mt][nt][3] * 0.125f);
                }
        }
        __syncthreads();   // S_raw[c] + S_norm[c-1] visible

        // ---- B: AV[c-1]; then issue K[c+2] ----
        if (c >= 1) {
            const unsigned svb = sQV + (unsigned)((c - 1) & 1) * Vbs;
            const unsigned ssb = sS + (unsigned)((c - 1) & 1) * Sbs;
            unsigned as[2][4], bv[4][4];
#pragma unroll
            for (int mt = 0; mt < 2; mt++)
                ldsm4(as[mt][0], as[mt][1], as[mt][2], as[mt][3],
                      ssb + (unsigned)((h * 32 + mt * 16 + a_r) * 24 + a_c) * 2);
#pragma unroll
            for (int np = 0; np < 4; np++)
                ldsm4t(bv[np][0], bv[np][1], bv[np][2], bv[np][3],
                       svb + (unsigned)((h * ICH + bt_r) * 72 + np * 16 + bt_c) * 2);
#pragma unroll
            for (int mt = 0; mt < 2; mt++)
#pragma unroll
                for (int nt = 0; nt < 8; nt++)
                    mma16816(oacc[mt][nt], as[mt][0], as[mt][1], as[mt][2], as[mt][3],
                             bv[nt >> 1][(nt & 1) * 2], bv[nt >> 1][(nt & 1) * 2 + 1]);
        }
        if (c + 2 <= NIT - 1) loadChunk(Kg, sK + (unsigned)((c + 2) & 1) * Kbs, (c + 2) * ICH);
        // next iteration's A-top barrier separates the V/S overwrites from
        // this phase's reads.
    }
    __syncthreads();   // all AV reads done before Osm overwrites QV region

    // ---- epilogue: stage O to smem [ch=16j+h][k stride 40], uint4 writeout --
    __half* Osm = sm;   // 1024 x 40 halves = 40960 <= 98304 available
#pragma unroll
    for (int mt = 0; mt < 2; mt++) {
        int k0 = mt * 16 + (l >> 2);
#pragma unroll
        for (int nt = 0; nt < 8; nt++) {
            int j0 = nt * 8 + 2 * (l & 3);
            Osm[(16 * j0 + h) * 40 + k0]           = __float2half_rn(oacc[mt][nt][0]);
            Osm[(16 * (j0 + 1) + h) * 40 + k0]     = __float2half_rn(oacc[mt][nt][1]);
            Osm[(16 * j0 + h) * 40 + k0 + 8]       = __float2half_rn(oacc[mt][nt][2]);
            Osm[(16 * (j0 + 1) + h) * 40 + k0 + 8] = __float2half_rn(oacc[mt][nt][3]);
        }
    }
    __syncthreads();

    __half* Xb = g_Xt + (size_t)b * HH * SS;
#pragma unroll
    for (int e = 0; e < 8; e++) {
        int id = e * 512 + tid;            // 0..4095
        int kseg = (id & 3) * 8;
        int cc = id >> 2;                  // channel 0..1023
        uint4 val = *(const uint4*)&Osm[cc * 40 + kseg];
        *(uint4*)&Xb[(size_t)cc * SS + kbase + kseg] = val;
    }
}

// ---------------------------------------------------------------------------
// Output projection: out = X @ Wo^T + bias, 3-stage cp.async.
// BM=64 BN=128 BK=32; A read from Xt (channel-major) via trans ldmatrix.
// ---------------------------------------------------------------------------
__global__ void __launch_bounds__(256) outproj_gemm(const float* __restrict__ bias,
                                                    float* __restrict__ out) {
    const __half* Wo = g_W16[3];

    __shared__ __half At[3][32][72];
    __shared__ __half Bt[3][128][40];

    const int tid = threadIdx.x;
    const int bm = blockIdx.y * 64, bn = blockIdx.x * 128;
    const int b_ = bm >> 11, sbase = bm & 2047;
    const int w = tid >> 5, l = tid & 31;
    const int wm = w >> 2, wn = w & 3;

    const int arow = tid >> 3, aseg = (tid & 7) * 8;
    const int bc0 = tid, bc1 = tid + 256;
    const int br0 = bc0 >> 2, bs0 = (bc0 & 3) * 8;
    const int br1 = bc1 >> 2, bs1 = (bc1 & 3) * 8;

    const int at_r = (l & 7) + ((l >> 4) & 1) * 8;
    const int at_c = ((l >> 3) & 1) * 8;
    const int b_r = (l & 7) | ((l >> 1) & 8), b_c = l & 8;

    const unsigned sAt = sptr(&At[0][0][0]);
    const unsigned sBt = sptr(&Bt[0][0][0]);
    const unsigned Abs = 32 * 72 * 2, Bbs = 128 * 40 * 2;

    const __half* Abase = g_Xt + (size_t)b_ * HH * SS + sbase;

    auto issue = [&](int kb, int st) {
        cpa16(sAt + st * Abs + (unsigned)(arow * 72 + aseg) * 2,
              Abase + (size_t)(kb * 32 + arow) * SS + aseg);
        cpa16(sBt + st * Bbs + (unsigned)(br0 * 40 + bs0) * 2,
              Wo + (size_t)(bn + br0) * HH + kb * 32 + bs0);
        cpa16(sBt + st * Bbs + (unsigned)(br1 * 40 + bs1) * 2,
              Wo + (size_t)(bn + br1) * HH + kb * 32 + bs1);
        cpa_commit();
    };

    float acc[2][4][4];
#pragma unroll
    for (int mt = 0; mt < 2; mt++)
#pragma unroll
        for (int nt = 0; nt < 4; nt++)
#pragma unroll
            for (int r = 0; r < 4; r++) acc[mt][nt][r] = 0.f;

    issue(0, 0);
    issue(1, 1);

    const int NKB = HH / 32;
    for (int kb = 0; kb < NKB; kb++) {
        const int st = kb % 3;
        if (kb == NKB - 1) cpa_wait<0>(); else cpa_wait<1>();
        __syncthreads();
        if (kb + 2 < NKB) issue(kb + 2, (kb + 2) % 3);

#pragma unroll
        for (int ks = 0; ks < 2; ks++) {
            unsigned a[2][4], bfr[2][4];
#pragma unroll
            for (int mt = 0; mt < 2; mt++) {
                int r = ks * 16 + at_r;
                int c = wm * 32 + mt * 16 + at_c;
                ldsm4t(a[mt][0], a[mt][1], a[mt][2], a[mt][3],
                       sAt + st * Abs + (unsigned)(r * 72 + c) * 2);
            }
#pragma unroll
            for (int np = 0; np < 2; np++) {
                int r = wn * 32 + np * 16 + b_r;
                int c = ks * 16 + b_c;
                ldsm4(bfr[np][0], bfr[np][1], bfr[np][2], bfr[np][3],
                      sBt + st * Bbs + (unsigned)(r * 40 + c) * 2);
            }
#pragma unroll
            for (int mt = 0; mt < 2; mt++)
#pragma unroll
                for (int nt = 0; nt < 4; nt++)
                    mma16816(acc[mt][nt], a[mt][0], a[mt][1], a[mt][2], a[mt][3],
                             bfr[nt >> 1][(nt & 1) * 2], bfr[nt >> 1][(nt & 1) * 2 + 1]);
        }
        __syncthreads();
    }

#pragma unroll
    for (int nt = 0; nt < 4; nt++) {
        int c0 = bn + wn * 32 + nt * 8 + 2 * (l & 3);
        float bv0 = bias[c0], bv1 = bias[c0 + 1];
#pragma unroll
        for (int mt = 0; mt < 2; mt++) {
            int r0 = bm + wm * 32 + mt * 16 + (l >> 2);
            float2 v0 = make_float2(acc[mt][nt][0] + bv0, acc[mt][nt][1] + bv1);
            float2 v1 = make_float2(acc[mt][nt][2] + bv0, acc[mt][nt][3] + bv1);
            *(float2*)&out[(size_t)r0 * HH + c0] = v0;
            *(float2*)&out[(size_t)(r0 + 8) * HH + c0] = v1;
        }
    }
}

// ---------------------------------------------------------------------------
// Launch
// ---------------------------------------------------------------------------
extern "C" void kernel_launch(void* const* d_in, const int* in_sizes, int n_in,
                              void* d_out, int out_size)
{
    const float* KEY   = (const float*)d_in[0];
    const float* VALUE = (const float*)d_in[1];
    const float* QUERY = (const float*)d_in[2];
    const float* Wk_w  = (const float*)d_in[3];
    const float* Wk_b  = (const float*)d_in[4];
    const float* Wq_w  = (const float*)d_in[5];
    const float* Wq_b  = (const float*)d_in[6];
    const float* Wv_w  = (const float*)d_in[7];
    const float* Wv_b  = (const float*)d_in[8];
    const float* Wo_w  = (const float*)d_in[9];
    const float* Wo_b  = (const float*)d_in[10];
    float* out = (float*)d_out;

    const int fsm = (36864 + 2 * 18432 + 2 * 12288) * 2;   // 196,608 B
    static bool attr_done = false;
    if (!attr_done) {
        cudaFuncSetAttribute(attn_fused, cudaFuncAttributeMaxDynamicSharedMemorySize, fsm);
        attr_done = true;
    }

    cvt_all<<<TOT4 / 512, 256>>>((const float4*)KEY, (const float4*)QUERY,
                                 (const float4*)VALUE, (const float4*)Wk_w,
                                 (const float4*)Wq_w, (const float4*)Wv_w,
                                 (const float4*)Wo_w);

    dim3 pg(HH / 128, (BB * SS) / 128, 3);         // 768 CTAs
    proj_fused<<<pg, 256>>>(Wk_b, Wq_b, Wv_b);

    dim3 fg(SS / 32, BB);                          // (64, 2) = 128 CTAs
    attn_fused<<<fg, 512, fsm>>>();

    dim3 og(HH / 128, (BB * SS) / 64);             // (8, 64)
    outproj_gemm<<<og, 256>>>(Wo_b, out);
}